// round 13
// baseline (speedup 1.0000x reference)
#include <cuda_runtime.h>
#include <math.h>
#include <float.h>
#include <stdint.h>

// ---------------------------------------------------------------------------
// Supernetwork: backbone (3x conv+BN+relu+pool) -> beam search -> MoE dispatch
// B=2048, BEAMS=4, DEPTH=3, HID=128, NOPS=4
//
// Round-12:
//  * conv1 persistent (152 blocks, weights loaded once, atomic image
//    stealing; counter reset by moe_step(step=2) at end of each replay).
//  * moe_step: 64 rows/block -> half the expert-weight reloads, one clean
//    wave of working blocks.
//  * conv2/conv3 persistent, fused pools, fused bucketing unchanged.
//  * Determinism: work order varies but per-item outputs are pure functions
//    of inputs; no float atomics; fixed-order FP reductions.
// ---------------------------------------------------------------------------

#define NB 2048
#define MROWS 64

// ------------------------------ scratch ------------------------------------
__device__ float g_buf1[(size_t)NB * 30 * 30 * 32];  // conv1 out, NHWC
__device__ float g_buf3[(size_t)NB * 13 * 13 * 32];  // conv2 out, NHWC
__device__ float g_buf5[(size_t)NB * 16 * 32];       // conv3 out, NHWC (4x4)
__device__ float g_h0[(size_t)NB * 128];             // backbone feature
__device__ float g_hid[(size_t)NB * 4 * 128];        // dispatch state
__device__ float g_psum[32 * NB];
__device__ float g_psq[32 * NB];
__device__ float g_scale[3][32];
__device__ float g_shift[3][32];
__device__ int   g_op[3 * NB * 4];
__device__ float g_pv[3 * NB * 4];
__device__ int   g_cnt[3][4];                        // rows per (step, expert)
__device__ int   g_ridx[3 * 4 * NB * 4];             // bucketed row indices
__device__ unsigned int g_ctr1;                      // conv1 work counter
__device__ unsigned int g_ctr2;                      // conv2 work counter
__device__ unsigned int g_ctr3;                      // conv3 work counter

// --------------------------- f32x2 helpers ---------------------------------
typedef unsigned long long u64t;

__device__ __forceinline__ void ffma2(u64t& c, u64t a, u64t b) {
    asm("fma.rn.f32x2 %0, %1, %2, %0;" : "+l"(c) : "l"(a), "l"(b));
}
__device__ __forceinline__ u64t splat2(float v) {
    u64t r;
    asm("mov.b64 %0, {%1, %1};" : "=l"(r) : "r"(__float_as_uint(v)));
    return r;
}
__device__ __forceinline__ float lo32(u64t v) { return __uint_as_float((unsigned)v); }
__device__ __forceinline__ float hi32(u64t v) { return __uint_as_float((unsigned)(v >> 32)); }

__device__ __forceinline__ float4 bnrelu4(float4 v, float4 sc, float4 sh) {
    float4 r;
    r.x = fmaxf(v.x * sc.x + sh.x, 0.f);
    r.y = fmaxf(v.y * sc.y + sh.y, 0.f);
    r.z = fmaxf(v.z * sc.z + sh.z, 0.f);
    r.w = fmaxf(v.w * sc.w + sh.w, 0.f);
    return r;
}

// -------- conv1: persistent, 3->32, 32x32 -> 30x30, fused stats ------------
__global__ __launch_bounds__(960, 1) void conv1_kernel(
    const float* __restrict__ x, const float* __restrict__ w,
    const float* __restrict__ bias)
{
    __shared__ float s_img[3 * 1024];
    __shared__ float s_w[27 * 32];
    __shared__ float s_b[32];
    __shared__ float s_ss[32][60];
    __shared__ float s_sq[32][60];
    __shared__ int s_imgidx;
    int tid = threadIdx.x;

    if (tid < 864) {
        int oc = tid / 27, k = tid % 27;
        s_w[k * 32 + oc] = w[tid];
    }
    if (tid < 32) s_b[tid] = bias[tid];

    int half = tid / 480;
    int rem  = tid % 480;
    int ocp = rem & 15;
    int row = rem >> 4;
    int ox0 = half * 15;

    while (true) {
        __syncthreads();   // weights ready / previous iteration fully done
        if (tid == 0) s_imgidx = (int)atomicAdd(&g_ctr1, 1u);
        __syncthreads();
        int img = s_imgidx;
        if (img >= NB) break;

        const float* xb = x + (size_t)img * 3072;
        for (int i = tid; i < 768; i += 960)
            ((float4*)s_img)[i] = ((const float4*)xb)[i];
        __syncthreads();

        u64t acc[15];
        u64t bv = *(const u64t*)(s_b + ocp * 2);
#pragma unroll
        for (int i = 0; i < 15; i++) acc[i] = bv;

#pragma unroll
        for (int ic = 0; ic < 3; ic++) {
#pragma unroll
            for (int ky = 0; ky < 3; ky++) {
                const float* irow = s_img + ic * 1024 + (row + ky) * 32;
                float in[17];
                if (half == 0) {
#pragma unroll
                    for (int i = 0; i < 4; i++) {
                        float4 v4 = ((const float4*)irow)[i];
                        in[4 * i] = v4.x; in[4 * i + 1] = v4.y;
                        in[4 * i + 2] = v4.z; in[4 * i + 3] = v4.w;
                    }
                    in[16] = irow[16];
                } else {
                    in[0] = irow[15];
#pragma unroll
                    for (int i = 0; i < 4; i++) {
                        float4 v4 = ((const float4*)(irow + 16))[i];
                        in[4 * i + 1] = v4.x; in[4 * i + 2] = v4.y;
                        in[4 * i + 3] = v4.z; in[4 * i + 4] = v4.w;
                    }
                }
#pragma unroll
                for (int kx = 0; kx < 3; kx++) {
                    u64t wv = *(const u64t*)(s_w + ((ic * 3 + ky) * 3 + kx) * 32 + ocp * 2);
#pragma unroll
                    for (int i = 0; i < 15; i++)
                        ffma2(acc[i], wv, splat2(in[i + kx]));
                }
            }
        }
        u64t* ob = (u64t*)(g_buf1 + (((size_t)img * 30 + row) * 30 + ox0) * 32 + 2 * ocp);
        float slo = 0.f, qlo = 0.f, shi = 0.f, qhi = 0.f;
#pragma unroll
        for (int i = 0; i < 15; i++) {
            u64t v = acc[i];
            ob[i * 16] = v;
            float a = lo32(v), b2 = hi32(v);
            slo += a; qlo += a * a; shi += b2; qhi += b2 * b2;
        }
        int rh = row + 30 * half;
        s_ss[2 * ocp][rh] = slo; s_sq[2 * ocp][rh] = qlo;
        s_ss[2 * ocp + 1][rh] = shi; s_sq[2 * ocp + 1][rh] = qhi;
        __syncthreads();
        if (tid < 32) {
            float s = 0.f, q = 0.f;
#pragma unroll
            for (int r = 0; r < 60; r++) { s += s_ss[tid][r]; q += s_sq[tid][r]; }
            g_psum[tid * NB + img] = s;
            g_psq[tid * NB + img] = q;
        }
    }
}

// Per-channel reduction over 2048 images (fixed pairwise order) -> scale/shift.
// Also resets the next stage's work counters (runs between conv stages).
__global__ __launch_bounds__(256) void reduce_stats_kernel(
    int stage, float invN,
    const float* __restrict__ gamma, const float* __restrict__ beta)
{
    __shared__ float ss[256], sq[256];
    int c = blockIdx.x;
    int t = threadIdx.x;
    if (blockIdx.x == 0) {
        if (stage == 0 && t == 0) g_ctr2 = 0u;
        if (stage == 1 && t == 0) g_ctr3 = 0u;
        if (stage == 2 && t < 12) (&g_cnt[0][0])[t] = 0;
    }
    float s = 0.f, q = 0.f;
#pragma unroll
    for (int k = 0; k < NB / 256; k++) {
        int img = t + k * 256;
        s += g_psum[c * NB + img];
        q += g_psq[c * NB + img];
    }
    ss[t] = s; sq[t] = q;
    __syncthreads();
#pragma unroll
    for (int off = 128; off; off >>= 1) {
        if (t < off) { ss[t] += ss[t + off]; sq[t] += sq[t + off]; }
        __syncthreads();
    }
    if (t == 0) {
        float mu = ss[0] * invN;
        float var = sq[0] * invN - mu * mu;
        float sc = gamma[c] * rsqrtf(var + 1e-5f);
        g_scale[stage][c] = sc;
        g_shift[stage][c] = beta[c] - mu * sc;
    }
}

// ------- conv2: persistent, 2 imgs/iteration, fused pool1 load -------------
__global__ __launch_bounds__(448, 2) void conv2_kernel(
    const float* __restrict__ w, const float* __restrict__ bias)
{
    extern __shared__ float sm[];
    float* s_img = sm;            // 2 * 32*15*16 = 15360
    float* s_w = sm + 15360;      // 9216
    __shared__ float s_b[32];
    __shared__ float s_ss[2][32][13];
    __shared__ float s_sq[2][32][13];
    __shared__ int s_pair;
    int tid = threadIdx.x;

    for (int i = tid; i < 9216; i += 448) {
        int oc = i / 288, r = i % 288;
        s_w[r * 32 + oc] = w[i];
    }
    if (tid < 32) s_b[tid] = bias[tid];

    while (true) {
        __syncthreads();
        if (tid == 0) s_pair = (int)atomicAdd(&g_ctr2, 1u);
        __syncthreads();
        int img0 = s_pair * 2;
        if (img0 >= NB) break;

        for (int i = tid; i < 3600; i += 448) {
            int sub = i / 1800, j = i % 1800;
            int c4 = j & 7, p = j >> 3;          // p = oy*15+ox
            int oy = p / 15, ox = p % 15;
            const float4* b = (const float4*)(g_buf1
                + (((size_t)(img0 + sub) * 30 + 2 * oy) * 30 + 2 * ox) * 32) + c4;
            float4 sc = ((const float4*)g_scale[0])[c4];
            float4 sh = ((const float4*)g_shift[0])[c4];
            float4 a0 = bnrelu4(b[0], sc, sh);
            float4 a1 = bnrelu4(b[8], sc, sh);
            float4 a2 = bnrelu4(b[240], sc, sh);
            float4 a3 = bnrelu4(b[248], sc, sh);
            int base = sub * 7680 + oy * 16 + ox;
            s_img[base + (4 * c4 + 0) * 240] = (a0.x + a1.x + a2.x + a3.x) * 0.25f;
            s_img[base + (4 * c4 + 1) * 240] = (a0.y + a1.y + a2.y + a3.y) * 0.25f;
            s_img[base + (4 * c4 + 2) * 240] = (a0.z + a1.z + a2.z + a3.z) * 0.25f;
            s_img[base + (4 * c4 + 3) * 240] = (a0.w + a1.w + a2.w + a3.w) * 0.25f;
        }
        __syncthreads();

        int sub = tid / 224;
        int local = tid % 224;
        if (local < 208) {
            int ocp = local & 15;
            int row = local >> 4;
            const float* imgbase = s_img + sub * 7680;
            u64t acc[13];
            u64t bv = *(const u64t*)(s_b + ocp * 2);
#pragma unroll
            for (int i = 0; i < 13; i++) acc[i] = bv;

            for (int ic = 0; ic < 32; ic++) {
#pragma unroll
                for (int ky = 0; ky < 3; ky++) {
                    const float4* irow4 = (const float4*)(imgbase + ic * 240 + (row + ky) * 16);
                    float in[16];
#pragma unroll
                    for (int i = 0; i < 4; i++) {
                        float4 v4 = irow4[i];
                        in[4 * i] = v4.x; in[4 * i + 1] = v4.y;
                        in[4 * i + 2] = v4.z; in[4 * i + 3] = v4.w;
                    }
#pragma unroll
                    for (int kx = 0; kx < 3; kx++) {
                        u64t wv = *(const u64t*)(s_w + (ic * 9 + ky * 3 + kx) * 32 + ocp * 2);
#pragma unroll
                        for (int ox = 0; ox < 13; ox++)
                            ffma2(acc[ox], wv, splat2(in[ox + kx]));
                    }
                }
            }
            u64t* ob = (u64t*)(g_buf3 + (((size_t)(img0 + sub) * 13 + row) * 13) * 32 + 2 * ocp);
            float slo = 0.f, qlo = 0.f, shi = 0.f, qhi = 0.f;
#pragma unroll
            for (int ox = 0; ox < 13; ox++) {
                u64t v = acc[ox];
                ob[ox * 16] = v;
                float a = lo32(v), b2 = hi32(v);
                slo += a; qlo += a * a; shi += b2; qhi += b2 * b2;
            }
            s_ss[sub][2 * ocp][row] = slo; s_sq[sub][2 * ocp][row] = qlo;
            s_ss[sub][2 * ocp + 1][row] = shi; s_sq[sub][2 * ocp + 1][row] = qhi;
        }
        __syncthreads();
        if (tid < 64) {
            int ssub = tid >> 5, c = tid & 31;
            float s = 0.f, q = 0.f;
#pragma unroll
            for (int r = 0; r < 13; r++) { s += s_ss[ssub][c][r]; q += s_sq[ssub][c][r]; }
            g_psum[c * NB + img0 + ssub] = s;
            g_psq[c * NB + img0 + ssub] = q;
        }
    }
}

// ------- conv3: persistent, 4 imgs/iteration, fused pool2 load -------------
__global__ __launch_bounds__(256, 3) void conv3_kernel(
    const float* __restrict__ w, const float* __restrict__ bias)
{
    extern __shared__ float sm[];
    float* s_img = sm;            // 4 * 32*6*8 = 6144
    float* s_w = sm + 6144;       // 9216
    __shared__ float s_b[32];
    __shared__ float s_ss[4][32][4];
    __shared__ float s_sq[4][32][4];
    __shared__ int s_chunk;
    int tid = threadIdx.x;

    for (int i = tid; i < 9216; i += 256) {
        int oc = i / 288, r = i % 288;
        s_w[r * 32 + oc] = w[i];
    }
    if (tid < 32) s_b[tid] = bias[tid];

    while (true) {
        __syncthreads();
        if (tid == 0) s_chunk = (int)atomicAdd(&g_ctr3, 1u);
        __syncthreads();
        int img0 = s_chunk * 4;
        if (img0 >= NB) break;

        for (int i = tid; i < 1152; i += 256) {
            int il = i / 288, j = i % 288;
            int c4 = j & 7, p = j >> 3;          // p = oy*6+ox
            int oy = p / 6, ox = p % 6;
            const float4* b = (const float4*)(g_buf3
                + (((size_t)(img0 + il) * 13 + 2 * oy) * 13 + 2 * ox) * 32) + c4;
            float4 sc = ((const float4*)g_scale[1])[c4];
            float4 sh = ((const float4*)g_shift[1])[c4];
            float4 a0 = bnrelu4(b[0], sc, sh);
            float4 a1 = bnrelu4(b[8], sc, sh);
            float4 a2 = bnrelu4(b[104], sc, sh);
            float4 a3 = bnrelu4(b[112], sc, sh);
            int base = il * 1536 + oy * 8 + ox;
            s_img[base + (4 * c4 + 0) * 48] = (a0.x + a1.x + a2.x + a3.x) * 0.25f;
            s_img[base + (4 * c4 + 1) * 48] = (a0.y + a1.y + a2.y + a3.y) * 0.25f;
            s_img[base + (4 * c4 + 2) * 48] = (a0.z + a1.z + a2.z + a3.z) * 0.25f;
            s_img[base + (4 * c4 + 3) * 48] = (a0.w + a1.w + a2.w + a3.w) * 0.25f;
        }
        __syncthreads();

        int ocp = tid & 15;
        int oy = (tid >> 4) & 3;
        int il = tid >> 6;
        const float* imgbase = s_img + il * 1536;
        u64t acc[4];
        u64t bv = *(const u64t*)(s_b + ocp * 2);
#pragma unroll
        for (int i = 0; i < 4; i++) acc[i] = bv;

        for (int ic = 0; ic < 32; ic++) {
#pragma unroll
            for (int ky = 0; ky < 3; ky++) {
                const float* irow = imgbase + ic * 48 + (oy + ky) * 8;
                float in[6];
                float4 v4 = *(const float4*)irow;
                in[0] = v4.x; in[1] = v4.y; in[2] = v4.z; in[3] = v4.w;
                in[4] = irow[4]; in[5] = irow[5];
#pragma unroll
                for (int kx = 0; kx < 3; kx++) {
                    u64t wv = *(const u64t*)(s_w + (ic * 9 + ky * 3 + kx) * 32 + ocp * 2);
#pragma unroll
                    for (int ox = 0; ox < 4; ox++)
                        ffma2(acc[ox], wv, splat2(in[ox + kx]));
                }
            }
        }
        u64t* ob = (u64t*)(g_buf5 + ((size_t)(img0 + il) * 16 + oy * 4) * 32 + 2 * ocp);
        float slo = 0.f, qlo = 0.f, shi = 0.f, qhi = 0.f;
#pragma unroll
        for (int ox = 0; ox < 4; ox++) {
            u64t v = acc[ox];
            ob[ox * 16] = v;
            float a = lo32(v), b2 = hi32(v);
            slo += a; qlo += a * a; shi += b2; qhi += b2 * b2;
        }
        s_ss[il][2 * ocp][oy] = slo; s_sq[il][2 * ocp][oy] = qlo;
        s_ss[il][2 * ocp + 1][oy] = shi; s_sq[il][2 * ocp + 1][oy] = qhi;
        __syncthreads();
        if (tid < 128) {
            int iimg = tid >> 5, c = tid & 31;
            float s = 0.f, q = 0.f;
#pragma unroll
            for (int r = 0; r < 4; r++) { s += s_ss[iimg][c][r]; q += s_sq[iimg][c][r]; }
            g_psum[c * NB + img0 + iimg] = s;
            g_psq[c * NB + img0 + iimg] = q;
        }
    }
}

// ------------- beam search (+ fused pool3, + fused MoE bucketing) ----------
__device__ __forceinline__ float warp_sum(float v) {
#pragma unroll
    for (int off = 16; off; off >>= 1) v += __shfl_down_sync(0xffffffffu, v, off);
    return v;
}

__global__ __launch_bounds__(128) void beam_kernel(
    const float* __restrict__ W_hh, const float* __restrict__ b_h,
    const float* __restrict__ E_op, const float* __restrict__ W_ho,
    const float* __restrict__ b_ho)
{
    __shared__ float s_h0[128];
    __shared__ float s_h[4][128];
    __shared__ float s_hn[4][128];
    __shared__ float s_Who[512];
    __shared__ float s_logits[4][4];
    __shared__ float s_scores[4];
    __shared__ int   s_op[4];
    __shared__ int   s_src[4];

    int n = blockIdx.x;
    int tid = threadIdx.x;
    int warp = tid >> 5, lane = tid & 31;

    // fused pool3
    {
        int c = tid >> 2, p = tid & 3;
        int oy = p >> 1, ox = p & 1;
        const float* b = g_buf5 + ((size_t)n * 16 + (2 * oy) * 4 + 2 * ox) * 32 + c;
        float sc = g_scale[2][c], sh = g_shift[2][c];
        float v = fmaxf(b[0] * sc + sh, 0.f) + fmaxf(b[32] * sc + sh, 0.f)
                + fmaxf(b[128] * sc + sh, 0.f) + fmaxf(b[160] * sc + sh, 0.f);
        v *= 0.25f;
        s_h0[tid] = v;
        g_h0[(size_t)n * 128 + tid] = v;
    }
#pragma unroll
    for (int i = 0; i < 4; i++) s_Who[i * 128 + tid] = W_ho[i * 128 + tid];
    __syncthreads();

    {
        float a = 0.f;
        for (int d = lane; d < 128; d += 32) a += s_h0[d] * s_Who[d * 4 + warp];
        a = warp_sum(a);
        if (lane == 0) s_logits[0][warp] = a + b_ho[warp];
    }
    __syncthreads();

    if (tid == 0) {
        float l[4], e[4];
        float m = -FLT_MAX;
#pragma unroll
        for (int o = 0; o < 4; o++) { l[o] = s_logits[0][o]; m = fmaxf(m, l[o]); }
        float sum = 0.f;
#pragma unroll
        for (int o = 0; o < 4; o++) { e[o] = expf(l[o] - m); sum += e[o]; }
        float logsum = logf(sum);
        float inv = 1.f / sum;
        bool used[4] = {false, false, false, false};
        for (int b = 0; b < 4; b++) {
            int best = -1; float bv = -FLT_MAX;
            for (int o = 0; o < 4; o++) {
                float lp = l[o] - m - logsum;
                if (!used[o] && lp > bv) { bv = lp; best = o; }
            }
            used[best] = true;
            s_scores[b] = bv;
            s_op[b] = best;
            g_op[0 * (NB * 4) + n * 4 + b] = best;
            g_pv[0 * (NB * 4) + n * 4 + b] = e[best] * inv;
        }
    }
    __syncthreads();

    {
        float common = 0.f;
#pragma unroll 8
        for (int k = 0; k < 128; k++) common += s_h0[k] * W_hh[k * 128 + tid];
        float bh = b_h[tid];
#pragma unroll
        for (int b = 0; b < 4; b++)
            s_h[b][tid] = tanhf(common + E_op[s_op[b] * 128 + tid] + bh);
    }
    __syncthreads();

    for (int step = 1; step < 3; step++) {
        {
            float a0 = 0.f, a1 = 0.f, a2 = 0.f, a3 = 0.f;
            for (int d = lane; d < 128; d += 32) {
                float v = s_h[warp][d];
                a0 += v * s_Who[d * 4 + 0];
                a1 += v * s_Who[d * 4 + 1];
                a2 += v * s_Who[d * 4 + 2];
                a3 += v * s_Who[d * 4 + 3];
            }
            a0 = warp_sum(a0); a1 = warp_sum(a1); a2 = warp_sum(a2); a3 = warp_sum(a3);
            if (lane == 0) {
                s_logits[warp][0] = a0 + b_ho[0];
                s_logits[warp][1] = a1 + b_ho[1];
                s_logits[warp][2] = a2 + b_ho[2];
                s_logits[warp][3] = a3 + b_ho[3];
            }
        }
        __syncthreads();

        if (tid == 0) {
            float cand[16], probs[16];
            for (int b = 0; b < 4; b++) {
                float l[4], e[4];
                float m = -FLT_MAX;
#pragma unroll
                for (int o = 0; o < 4; o++) { l[o] = s_logits[b][o]; m = fmaxf(m, l[o]); }
                float sum = 0.f;
#pragma unroll
                for (int o = 0; o < 4; o++) { e[o] = expf(l[o] - m); sum += e[o]; }
                float logsum = logf(sum);
                float inv = 1.f / sum;
#pragma unroll
                for (int o = 0; o < 4; o++) {
                    cand[b * 4 + o] = s_scores[b] + (l[o] - m - logsum);
                    probs[b * 4 + o] = e[o] * inv;
                }
            }
            bool used[16];
            for (int i = 0; i < 16; i++) used[i] = false;
            float ns[4];
            for (int b = 0; b < 4; b++) {
                int best = -1; float bv = -FLT_MAX;
                for (int f = 0; f < 16; f++)
                    if (!used[f] && cand[f] > bv) { bv = cand[f]; best = f; }
                used[best] = true;
                ns[b] = bv;
                int src = best >> 2, op = best & 3;
                s_src[b] = src; s_op[b] = op;
                g_op[step * (NB * 4) + n * 4 + b] = op;
                g_pv[step * (NB * 4) + n * 4 + b] = probs[best];
            }
#pragma unroll
            for (int b = 0; b < 4; b++) s_scores[b] = ns[b];
        }
        __syncthreads();

        if (step < 2) {
            int r0 = s_src[0], r1 = s_src[1], r2 = s_src[2], r3 = s_src[3];
            float a0 = 0.f, a1 = 0.f, a2 = 0.f, a3 = 0.f;
#pragma unroll 4
            for (int k = 0; k < 128; k++) {
                float wv = W_hh[k * 128 + tid];
                a0 += s_h[r0][k] * wv;
                a1 += s_h[r1][k] * wv;
                a2 += s_h[r2][k] * wv;
                a3 += s_h[r3][k] * wv;
            }
            float bh = b_h[tid];
            s_hn[0][tid] = tanhf(a0 + E_op[s_op[0] * 128 + tid] + bh);
            s_hn[1][tid] = tanhf(a1 + E_op[s_op[1] * 128 + tid] + bh);
            s_hn[2][tid] = tanhf(a2 + E_op[s_op[2] * 128 + tid] + bh);
            s_hn[3][tid] = tanhf(a3 + E_op[s_op[3] * 128 + tid] + bh);
            __syncthreads();
#pragma unroll
            for (int b = 0; b < 4; b++) s_h[b][tid] = s_hn[b][tid];
            __syncthreads();
        }
    }

    // fused MoE bucketing
    if (tid < 12) {
        int step = tid >> 2, b = tid & 3;
        int m = n * 4 + b;
        int op = g_op[step * (NB * 4) + m];
        float p = g_pv[step * (NB * 4) + m];
        int e = (p > 0.f) ? op : 0;
        int pos = atomicAdd(&g_cnt[step][e], 1);
        g_ridx[(step * 4 + e) * (NB * 4) + pos] = m;
    }
}

// ---------------------- sorted MoE dispatch --------------------------------
// One step of dispatch, MROWS=64 rows per block. step==2 additionally
// computes the final 128->10 projection from smem, and resets g_ctr1 for the
// next graph replay.
__global__ __launch_bounds__(256) void moe_step_kernel(
    const float* __restrict__ exp_w, const float* __restrict__ exp_b,
    const float* __restrict__ out_w, const float* __restrict__ out_b,
    float* __restrict__ out, int step)
{
    extern __shared__ float sm[];
    float* s_w = sm;              // 16384 floats
    float* buf = sm + 16384;      // 64 x 128 = 8192
    float* s_outw = sm + 24576;   // 1280 floats (step==2 only)
    __shared__ float s_b[128];
    __shared__ float s_outb[10];
    __shared__ int   s_rows[MROWS];
    __shared__ float s_p[MROWS];
    __shared__ int   s_cnt;

    int e = blockIdx.y;
    int tid = threadIdx.x;
    if (step == 2 && blockIdx.x == 0 && blockIdx.y == 0 && tid == 0)
        g_ctr1 = 0u;   // reset conv1 work counter for the next replay
    if (tid == 0) s_cnt = g_cnt[step][e];
    __syncthreads();
    int base = blockIdx.x * MROWS;
    if (base >= s_cnt) return;
    int nrows = min(MROWS, s_cnt - base);

    if (tid < nrows) {
        int m = g_ridx[(step * 4 + e) * (NB * 4) + base + tid];
        s_rows[tid] = m;
        s_p[tid] = g_pv[step * (NB * 4) + m];
    }
    if (step == 2) {
        for (int i = tid; i < 1280; i += 256) s_outw[i] = out_w[i];
        if (tid < 10) s_outb[tid] = out_b[tid];
    }
    __syncthreads();

    if (e == 3) {   // identity: out = relu(hid * p)
        if (step < 2) {
            for (int i = tid; i < nrows * 128; i += 256) {
                int r = i >> 7, j = i & 127;
                int m = s_rows[r];
                float v = (step == 0) ? g_h0[(size_t)(m >> 2) * 128 + j]
                                      : g_hid[(size_t)m * 128 + j];
                g_hid[(size_t)m * 128 + j] = fmaxf(v * s_p[r], 0.f);
            }
            return;
        }
        for (int i = tid; i < nrows * 128; i += 256) {
            int r = i >> 7, j = i & 127;
            float v = g_hid[(size_t)s_rows[r] * 128 + j];
            buf[i] = fmaxf(v * s_p[r], 0.f);
        }
        __syncthreads();
        for (int i = tid; i < nrows * 10; i += 256) {
            int r = i / 10, o = i % 10;
            float a = s_outb[o];
            const float* hp = buf + r * 128;
#pragma unroll 8
            for (int d = 0; d < 128; d++) a += hp[d] * s_outw[d * 10 + o];
            out[(size_t)s_rows[r] * 10 + o] = a;
        }
        return;
    }

    for (int i = tid; i < 16384; i += 256) s_w[i] = exp_w[e * 16384 + i];
    if (tid < 128) s_b[tid] = exp_b[e * 128 + tid];
    for (int i = tid; i < MROWS * 128; i += 256) {
        int r = i >> 7, j = i & 127;
        float v = 0.f;
        if (r < nrows) {
            int m = s_rows[r];
            v = (step == 0) ? g_h0[(size_t)(m >> 2) * 128 + j]
                            : g_hid[(size_t)m * 128 + j];
        }
        buf[i] = v;
    }
    __syncthreads();

    int cp = tid & 63, rowg = tid >> 6;
    int r0 = rowg * 16, j0 = cp * 2;
    u64t acc[16];
#pragma unroll
    for (int k = 0; k < 16; k++) acc[k] = 0ull;
    for (int d = 0; d < 128; d += 4) {
        u64t w0 = *(const u64t*)(s_w + (d + 0) * 128 + j0);
        u64t w1 = *(const u64t*)(s_w + (d + 1) * 128 + j0);
        u64t w2 = *(const u64t*)(s_w + (d + 2) * 128 + j0);
        u64t w3 = *(const u64t*)(s_w + (d + 3) * 128 + j0);
#pragma unroll
        for (int k = 0; k < 16; k++) {
            float4 h = *(const float4*)(buf + (r0 + k) * 128 + d);
            ffma2(acc[k], w0, splat2(h.x));
            ffma2(acc[k], w1, splat2(h.y));
            ffma2(acc[k], w2, splat2(h.z));
            ffma2(acc[k], w3, splat2(h.w));
        }
    }
    u64t b2 = *(const u64t*)(s_b + j0);

    if (step < 2) {
#pragma unroll
        for (int k = 0; k < 16; k++) {
            int r = r0 + k;
            if (r < nrows) {
                int m = s_rows[r];
                float v = s_p[r];
                float2 st;
                st.x = fmaxf((lo32(acc[k]) + lo32(b2)) * v, 0.f);
                st.y = fmaxf((hi32(acc[k]) + hi32(b2)) * v, 0.f);
                *(float2*)(g_hid + (size_t)m * 128 + j0) = st;
            }
        }
        return;
    }

    // step==2: write results back into buf, then project
    __syncthreads();   // all reads of buf done
#pragma unroll
    for (int k = 0; k < 16; k++) {
        int r = r0 + k;
        float v = s_p[r < nrows ? r : 0];
        float2 st;
        st.x = fmaxf((lo32(acc[k]) + lo32(b2)) * v, 0.f);
        st.y = fmaxf((hi32(acc[k]) + hi32(b2)) * v, 0.f);
        *(float2*)(buf + r * 128 + j0) = st;
    }
    __syncthreads();
    for (int i = tid; i < nrows * 10; i += 256) {
        int r = i / 10, o = i % 10;
        float a = s_outb[o];
        const float* hp = buf + r * 128;
#pragma unroll 8
        for (int d = 0; d < 128; d++) a += hp[d] * s_outw[d * 10 + o];
        out[(size_t)s_rows[r] * 10 + o] = a;
    }
}

// ---------------------------------------------------------------------------
extern "C" void kernel_launch(void* const* d_in, const int* in_sizes, int n_in,
                              void* d_out, int out_size)
{
    const float* x    = (const float*)d_in[0];
    const float* cw1  = (const float*)d_in[1];
    const float* cb1  = (const float*)d_in[2];
    const float* g1   = (const float*)d_in[3];
    const float* be1  = (const float*)d_in[4];
    const float* cw2  = (const float*)d_in[5];
    const float* cb2  = (const float*)d_in[6];
    const float* g2   = (const float*)d_in[7];
    const float* be2  = (const float*)d_in[8];
    const float* cw3  = (const float*)d_in[9];
    const float* cb3  = (const float*)d_in[10];
    const float* g3   = (const float*)d_in[11];
    const float* be3  = (const float*)d_in[12];
    const float* W_hh = (const float*)d_in[13];
    const float* b_h  = (const float*)d_in[14];
    const float* E_op = (const float*)d_in[15];
    const float* W_ho = (const float*)d_in[16];
    const float* b_ho = (const float*)d_in[17];
    const float* expw = (const float*)d_in[18];
    const float* expb = (const float*)d_in[19];
    const float* outw = (const float*)d_in[20];
    const float* outb = (const float*)d_in[21];
    float* out = (float*)d_out;

    cudaFuncSetAttribute(conv2_kernel, cudaFuncAttributeMaxDynamicSharedMemorySize,
                         (15360 + 9216) * 4);
    cudaFuncSetAttribute(conv3_kernel, cudaFuncAttributeMaxDynamicSharedMemorySize,
                         (6144 + 9216) * 4);
    cudaFuncSetAttribute(moe_step_kernel, cudaFuncAttributeMaxDynamicSharedMemorySize,
                         (16384 + MROWS * 128 + 1280) * 4);

    conv1_kernel<<<152, 960>>>(x, cw1, cb1);
    reduce_stats_kernel<<<32, 256>>>(0, 1.f / (NB * 900.f), g1, be1);

    conv2_kernel<<<304, 448, (15360 + 9216) * 4>>>(cw2, cb2);
    reduce_stats_kernel<<<32, 256>>>(1, 1.f / (NB * 169.f), g2, be2);

    conv3_kernel<<<456, 256, (6144 + 9216) * 4>>>(cw3, cb3);
    reduce_stats_kernel<<<32, 256>>>(2, 1.f / (NB * 16.f), g3, be3);

    beam_kernel<<<NB, 128>>>(W_hh, b_h, E_op, W_ho, b_ho);

    dim3 moe_grid(NB * 4 / MROWS, 4);
    size_t moe_smem = (16384 + MROWS * 128 + 1280) * 4;
    moe_step_kernel<<<moe_grid, 256, moe_smem>>>(expw, expb, outw, outb, out, 0);
    moe_step_kernel<<<moe_grid, 256, moe_smem>>>(expw, expb, outw, outb, out, 1);
    moe_step_kernel<<<moe_grid, 256, moe_smem>>>(expw, expb, outw, outb, out, 2);
}

// round 16
// speedup vs baseline: 1.0518x; 1.0518x over previous
#include <cuda_runtime.h>
#include <math.h>
#include <float.h>
#include <stdint.h>

// ---------------------------------------------------------------------------
// Supernetwork: backbone (3x conv+BN+relu+pool) -> beam search -> MoE dispatch
// B=2048, BEAMS=4, DEPTH=3, HID=128, NOPS=4
//
// Round-13:
//  * moe_step reverted to R11's 8-accumulator / 32-rows-per-block form
//    (the 64-row variant spilled registers -> R12 regression).
//  * conv1 stays persistent (152 blocks, weights loaded once; counter reset
//    by moe_step(step=2) at the end of each replay).
//  * conv2/conv3 persistent, fused pools, fused bucketing unchanged.
//  * Determinism: work order varies but per-item outputs are pure functions
//    of inputs; no float atomics; fixed-order FP reductions.
// ---------------------------------------------------------------------------

#define NB 2048

// ------------------------------ scratch ------------------------------------
__device__ float g_buf1[(size_t)NB * 30 * 30 * 32];  // conv1 out, NHWC
__device__ float g_buf3[(size_t)NB * 13 * 13 * 32];  // conv2 out, NHWC
__device__ float g_buf5[(size_t)NB * 16 * 32];       // conv3 out, NHWC (4x4)
__device__ float g_h0[(size_t)NB * 128];             // backbone feature
__device__ float g_hid[(size_t)NB * 4 * 128];        // dispatch state
__device__ float g_psum[32 * NB];
__device__ float g_psq[32 * NB];
__device__ float g_scale[3][32];
__device__ float g_shift[3][32];
__device__ int   g_op[3 * NB * 4];
__device__ float g_pv[3 * NB * 4];
__device__ int   g_cnt[3][4];                        // rows per (step, expert)
__device__ int   g_ridx[3 * 4 * NB * 4];             // bucketed row indices
__device__ unsigned int g_ctr1;                      // conv1 work counter
__device__ unsigned int g_ctr2;                      // conv2 work counter
__device__ unsigned int g_ctr3;                      // conv3 work counter

// --------------------------- f32x2 helpers ---------------------------------
typedef unsigned long long u64t;

__device__ __forceinline__ void ffma2(u64t& c, u64t a, u64t b) {
    asm("fma.rn.f32x2 %0, %1, %2, %0;" : "+l"(c) : "l"(a), "l"(b));
}
__device__ __forceinline__ u64t splat2(float v) {
    u64t r;
    asm("mov.b64 %0, {%1, %1};" : "=l"(r) : "r"(__float_as_uint(v)));
    return r;
}
__device__ __forceinline__ float lo32(u64t v) { return __uint_as_float((unsigned)v); }
__device__ __forceinline__ float hi32(u64t v) { return __uint_as_float((unsigned)(v >> 32)); }

__device__ __forceinline__ float4 bnrelu4(float4 v, float4 sc, float4 sh) {
    float4 r;
    r.x = fmaxf(v.x * sc.x + sh.x, 0.f);
    r.y = fmaxf(v.y * sc.y + sh.y, 0.f);
    r.z = fmaxf(v.z * sc.z + sh.z, 0.f);
    r.w = fmaxf(v.w * sc.w + sh.w, 0.f);
    return r;
}

// -------- conv1: persistent, 3->32, 32x32 -> 30x30, fused stats ------------
__global__ __launch_bounds__(960, 1) void conv1_kernel(
    const float* __restrict__ x, const float* __restrict__ w,
    const float* __restrict__ bias)
{
    __shared__ float s_img[3 * 1024];
    __shared__ float s_w[27 * 32];
    __shared__ float s_b[32];
    __shared__ float s_ss[32][60];
    __shared__ float s_sq[32][60];
    __shared__ int s_imgidx;
    int tid = threadIdx.x;

    if (tid < 864) {
        int oc = tid / 27, k = tid % 27;
        s_w[k * 32 + oc] = w[tid];
    }
    if (tid < 32) s_b[tid] = bias[tid];

    int half = tid / 480;
    int rem  = tid % 480;
    int ocp = rem & 15;
    int row = rem >> 4;
    int ox0 = half * 15;

    while (true) {
        __syncthreads();   // weights ready / previous iteration fully done
        if (tid == 0) s_imgidx = (int)atomicAdd(&g_ctr1, 1u);
        __syncthreads();
        int img = s_imgidx;
        if (img >= NB) break;

        const float* xb = x + (size_t)img * 3072;
        for (int i = tid; i < 768; i += 960)
            ((float4*)s_img)[i] = ((const float4*)xb)[i];
        __syncthreads();

        u64t acc[15];
        u64t bv = *(const u64t*)(s_b + ocp * 2);
#pragma unroll
        for (int i = 0; i < 15; i++) acc[i] = bv;

#pragma unroll
        for (int ic = 0; ic < 3; ic++) {
#pragma unroll
            for (int ky = 0; ky < 3; ky++) {
                const float* irow = s_img + ic * 1024 + (row + ky) * 32;
                float in[17];
                if (half == 0) {
#pragma unroll
                    for (int i = 0; i < 4; i++) {
                        float4 v4 = ((const float4*)irow)[i];
                        in[4 * i] = v4.x; in[4 * i + 1] = v4.y;
                        in[4 * i + 2] = v4.z; in[4 * i + 3] = v4.w;
                    }
                    in[16] = irow[16];
                } else {
                    in[0] = irow[15];
#pragma unroll
                    for (int i = 0; i < 4; i++) {
                        float4 v4 = ((const float4*)(irow + 16))[i];
                        in[4 * i + 1] = v4.x; in[4 * i + 2] = v4.y;
                        in[4 * i + 3] = v4.z; in[4 * i + 4] = v4.w;
                    }
                }
#pragma unroll
                for (int kx = 0; kx < 3; kx++) {
                    u64t wv = *(const u64t*)(s_w + ((ic * 3 + ky) * 3 + kx) * 32 + ocp * 2);
#pragma unroll
                    for (int i = 0; i < 15; i++)
                        ffma2(acc[i], wv, splat2(in[i + kx]));
                }
            }
        }
        u64t* ob = (u64t*)(g_buf1 + (((size_t)img * 30 + row) * 30 + ox0) * 32 + 2 * ocp);
        float slo = 0.f, qlo = 0.f, shi = 0.f, qhi = 0.f;
#pragma unroll
        for (int i = 0; i < 15; i++) {
            u64t v = acc[i];
            ob[i * 16] = v;
            float a = lo32(v), b2 = hi32(v);
            slo += a; qlo += a * a; shi += b2; qhi += b2 * b2;
        }
        int rh = row + 30 * half;
        s_ss[2 * ocp][rh] = slo; s_sq[2 * ocp][rh] = qlo;
        s_ss[2 * ocp + 1][rh] = shi; s_sq[2 * ocp + 1][rh] = qhi;
        __syncthreads();
        if (tid < 32) {
            float s = 0.f, q = 0.f;
#pragma unroll
            for (int r = 0; r < 60; r++) { s += s_ss[tid][r]; q += s_sq[tid][r]; }
            g_psum[tid * NB + img] = s;
            g_psq[tid * NB + img] = q;
        }
    }
}

// Per-channel reduction over 2048 images (fixed pairwise order) -> scale/shift.
// Also resets the next stage's work counters (runs between conv stages).
__global__ __launch_bounds__(256) void reduce_stats_kernel(
    int stage, float invN,
    const float* __restrict__ gamma, const float* __restrict__ beta)
{
    __shared__ float ss[256], sq[256];
    int c = blockIdx.x;
    int t = threadIdx.x;
    if (blockIdx.x == 0) {
        if (stage == 0 && t == 0) g_ctr2 = 0u;
        if (stage == 1 && t == 0) g_ctr3 = 0u;
        if (stage == 2 && t < 12) (&g_cnt[0][0])[t] = 0;
    }
    float s = 0.f, q = 0.f;
#pragma unroll
    for (int k = 0; k < NB / 256; k++) {
        int img = t + k * 256;
        s += g_psum[c * NB + img];
        q += g_psq[c * NB + img];
    }
    ss[t] = s; sq[t] = q;
    __syncthreads();
#pragma unroll
    for (int off = 128; off; off >>= 1) {
        if (t < off) { ss[t] += ss[t + off]; sq[t] += sq[t + off]; }
        __syncthreads();
    }
    if (t == 0) {
        float mu = ss[0] * invN;
        float var = sq[0] * invN - mu * mu;
        float sc = gamma[c] * rsqrtf(var + 1e-5f);
        g_scale[stage][c] = sc;
        g_shift[stage][c] = beta[c] - mu * sc;
    }
}

// ------- conv2: persistent, 2 imgs/iteration, fused pool1 load -------------
__global__ __launch_bounds__(448, 2) void conv2_kernel(
    const float* __restrict__ w, const float* __restrict__ bias)
{
    extern __shared__ float sm[];
    float* s_img = sm;            // 2 * 32*15*16 = 15360
    float* s_w = sm + 15360;      // 9216
    __shared__ float s_b[32];
    __shared__ float s_ss[2][32][13];
    __shared__ float s_sq[2][32][13];
    __shared__ int s_pair;
    int tid = threadIdx.x;

    for (int i = tid; i < 9216; i += 448) {
        int oc = i / 288, r = i % 288;
        s_w[r * 32 + oc] = w[i];
    }
    if (tid < 32) s_b[tid] = bias[tid];

    while (true) {
        __syncthreads();
        if (tid == 0) s_pair = (int)atomicAdd(&g_ctr2, 1u);
        __syncthreads();
        int img0 = s_pair * 2;
        if (img0 >= NB) break;

        for (int i = tid; i < 3600; i += 448) {
            int sub = i / 1800, j = i % 1800;
            int c4 = j & 7, p = j >> 3;          // p = oy*15+ox
            int oy = p / 15, ox = p % 15;
            const float4* b = (const float4*)(g_buf1
                + (((size_t)(img0 + sub) * 30 + 2 * oy) * 30 + 2 * ox) * 32) + c4;
            float4 sc = ((const float4*)g_scale[0])[c4];
            float4 sh = ((const float4*)g_shift[0])[c4];
            float4 a0 = bnrelu4(b[0], sc, sh);
            float4 a1 = bnrelu4(b[8], sc, sh);
            float4 a2 = bnrelu4(b[240], sc, sh);
            float4 a3 = bnrelu4(b[248], sc, sh);
            int base = sub * 7680 + oy * 16 + ox;
            s_img[base + (4 * c4 + 0) * 240] = (a0.x + a1.x + a2.x + a3.x) * 0.25f;
            s_img[base + (4 * c4 + 1) * 240] = (a0.y + a1.y + a2.y + a3.y) * 0.25f;
            s_img[base + (4 * c4 + 2) * 240] = (a0.z + a1.z + a2.z + a3.z) * 0.25f;
            s_img[base + (4 * c4 + 3) * 240] = (a0.w + a1.w + a2.w + a3.w) * 0.25f;
        }
        __syncthreads();

        int sub = tid / 224;
        int local = tid % 224;
        if (local < 208) {
            int ocp = local & 15;
            int row = local >> 4;
            const float* imgbase = s_img + sub * 7680;
            u64t acc[13];
            u64t bv = *(const u64t*)(s_b + ocp * 2);
#pragma unroll
            for (int i = 0; i < 13; i++) acc[i] = bv;

            for (int ic = 0; ic < 32; ic++) {
#pragma unroll
                for (int ky = 0; ky < 3; ky++) {
                    const float4* irow4 = (const float4*)(imgbase + ic * 240 + (row + ky) * 16);
                    float in[16];
#pragma unroll
                    for (int i = 0; i < 4; i++) {
                        float4 v4 = irow4[i];
                        in[4 * i] = v4.x; in[4 * i + 1] = v4.y;
                        in[4 * i + 2] = v4.z; in[4 * i + 3] = v4.w;
                    }
#pragma unroll
                    for (int kx = 0; kx < 3; kx++) {
                        u64t wv = *(const u64t*)(s_w + (ic * 9 + ky * 3 + kx) * 32 + ocp * 2);
#pragma unroll
                        for (int ox = 0; ox < 13; ox++)
                            ffma2(acc[ox], wv, splat2(in[ox + kx]));
                    }
                }
            }
            u64t* ob = (u64t*)(g_buf3 + (((size_t)(img0 + sub) * 13 + row) * 13) * 32 + 2 * ocp);
            float slo = 0.f, qlo = 0.f, shi = 0.f, qhi = 0.f;
#pragma unroll
            for (int ox = 0; ox < 13; ox++) {
                u64t v = acc[ox];
                ob[ox * 16] = v;
                float a = lo32(v), b2 = hi32(v);
                slo += a; qlo += a * a; shi += b2; qhi += b2 * b2;
            }
            s_ss[sub][2 * ocp][row] = slo; s_sq[sub][2 * ocp][row] = qlo;
            s_ss[sub][2 * ocp + 1][row] = shi; s_sq[sub][2 * ocp + 1][row] = qhi;
        }
        __syncthreads();
        if (tid < 64) {
            int ssub = tid >> 5, c = tid & 31;
            float s = 0.f, q = 0.f;
#pragma unroll
            for (int r = 0; r < 13; r++) { s += s_ss[ssub][c][r]; q += s_sq[ssub][c][r]; }
            g_psum[c * NB + img0 + ssub] = s;
            g_psq[c * NB + img0 + ssub] = q;
        }
    }
}

// ------- conv3: persistent, 4 imgs/iteration, fused pool2 load -------------
__global__ __launch_bounds__(256, 3) void conv3_kernel(
    const float* __restrict__ w, const float* __restrict__ bias)
{
    extern __shared__ float sm[];
    float* s_img = sm;            // 4 * 32*6*8 = 6144
    float* s_w = sm + 6144;       // 9216
    __shared__ float s_b[32];
    __shared__ float s_ss[4][32][4];
    __shared__ float s_sq[4][32][4];
    __shared__ int s_chunk;
    int tid = threadIdx.x;

    for (int i = tid; i < 9216; i += 256) {
        int oc = i / 288, r = i % 288;
        s_w[r * 32 + oc] = w[i];
    }
    if (tid < 32) s_b[tid] = bias[tid];

    while (true) {
        __syncthreads();
        if (tid == 0) s_chunk = (int)atomicAdd(&g_ctr3, 1u);
        __syncthreads();
        int img0 = s_chunk * 4;
        if (img0 >= NB) break;

        for (int i = tid; i < 1152; i += 256) {
            int il = i / 288, j = i % 288;
            int c4 = j & 7, p = j >> 3;          // p = oy*6+ox
            int oy = p / 6, ox = p % 6;
            const float4* b = (const float4*)(g_buf3
                + (((size_t)(img0 + il) * 13 + 2 * oy) * 13 + 2 * ox) * 32) + c4;
            float4 sc = ((const float4*)g_scale[1])[c4];
            float4 sh = ((const float4*)g_shift[1])[c4];
            float4 a0 = bnrelu4(b[0], sc, sh);
            float4 a1 = bnrelu4(b[8], sc, sh);
            float4 a2 = bnrelu4(b[104], sc, sh);
            float4 a3 = bnrelu4(b[112], sc, sh);
            int base = il * 1536 + oy * 8 + ox;
            s_img[base + (4 * c4 + 0) * 48] = (a0.x + a1.x + a2.x + a3.x) * 0.25f;
            s_img[base + (4 * c4 + 1) * 48] = (a0.y + a1.y + a2.y + a3.y) * 0.25f;
            s_img[base + (4 * c4 + 2) * 48] = (a0.z + a1.z + a2.z + a3.z) * 0.25f;
            s_img[base + (4 * c4 + 3) * 48] = (a0.w + a1.w + a2.w + a3.w) * 0.25f;
        }
        __syncthreads();

        int ocp = tid & 15;
        int oy = (tid >> 4) & 3;
        int il = tid >> 6;
        const float* imgbase = s_img + il * 1536;
        u64t acc[4];
        u64t bv = *(const u64t*)(s_b + ocp * 2);
#pragma unroll
        for (int i = 0; i < 4; i++) acc[i] = bv;

        for (int ic = 0; ic < 32; ic++) {
#pragma unroll
            for (int ky = 0; ky < 3; ky++) {
                const float* irow = imgbase + ic * 48 + (oy + ky) * 8;
                float in[6];
                float4 v4 = *(const float4*)irow;
                in[0] = v4.x; in[1] = v4.y; in[2] = v4.z; in[3] = v4.w;
                in[4] = irow[4]; in[5] = irow[5];
#pragma unroll
                for (int kx = 0; kx < 3; kx++) {
                    u64t wv = *(const u64t*)(s_w + (ic * 9 + ky * 3 + kx) * 32 + ocp * 2);
#pragma unroll
                    for (int ox = 0; ox < 4; ox++)
                        ffma2(acc[ox], wv, splat2(in[ox + kx]));
                }
            }
        }
        u64t* ob = (u64t*)(g_buf5 + ((size_t)(img0 + il) * 16 + oy * 4) * 32 + 2 * ocp);
        float slo = 0.f, qlo = 0.f, shi = 0.f, qhi = 0.f;
#pragma unroll
        for (int ox = 0; ox < 4; ox++) {
            u64t v = acc[ox];
            ob[ox * 16] = v;
            float a = lo32(v), b2 = hi32(v);
            slo += a; qlo += a * a; shi += b2; qhi += b2 * b2;
        }
        s_ss[il][2 * ocp][oy] = slo; s_sq[il][2 * ocp][oy] = qlo;
        s_ss[il][2 * ocp + 1][oy] = shi; s_sq[il][2 * ocp + 1][oy] = qhi;
        __syncthreads();
        if (tid < 128) {
            int iimg = tid >> 5, c = tid & 31;
            float s = 0.f, q = 0.f;
#pragma unroll
            for (int r = 0; r < 4; r++) { s += s_ss[iimg][c][r]; q += s_sq[iimg][c][r]; }
            g_psum[c * NB + img0 + iimg] = s;
            g_psq[c * NB + img0 + iimg] = q;
        }
    }
}

// ------------- beam search (+ fused pool3, + fused MoE bucketing) ----------
__device__ __forceinline__ float warp_sum(float v) {
#pragma unroll
    for (int off = 16; off; off >>= 1) v += __shfl_down_sync(0xffffffffu, v, off);
    return v;
}

__global__ __launch_bounds__(128) void beam_kernel(
    const float* __restrict__ W_hh, const float* __restrict__ b_h,
    const float* __restrict__ E_op, const float* __restrict__ W_ho,
    const float* __restrict__ b_ho)
{
    __shared__ float s_h0[128];
    __shared__ float s_h[4][128];
    __shared__ float s_hn[4][128];
    __shared__ float s_Who[512];
    __shared__ float s_logits[4][4];
    __shared__ float s_scores[4];
    __shared__ int   s_op[4];
    __shared__ int   s_src[4];

    int n = blockIdx.x;
    int tid = threadIdx.x;
    int warp = tid >> 5, lane = tid & 31;

    // fused pool3
    {
        int c = tid >> 2, p = tid & 3;
        int oy = p >> 1, ox = p & 1;
        const float* b = g_buf5 + ((size_t)n * 16 + (2 * oy) * 4 + 2 * ox) * 32 + c;
        float sc = g_scale[2][c], sh = g_shift[2][c];
        float v = fmaxf(b[0] * sc + sh, 0.f) + fmaxf(b[32] * sc + sh, 0.f)
                + fmaxf(b[128] * sc + sh, 0.f) + fmaxf(b[160] * sc + sh, 0.f);
        v *= 0.25f;
        s_h0[tid] = v;
        g_h0[(size_t)n * 128 + tid] = v;
    }
#pragma unroll
    for (int i = 0; i < 4; i++) s_Who[i * 128 + tid] = W_ho[i * 128 + tid];
    __syncthreads();

    {
        float a = 0.f;
        for (int d = lane; d < 128; d += 32) a += s_h0[d] * s_Who[d * 4 + warp];
        a = warp_sum(a);
        if (lane == 0) s_logits[0][warp] = a + b_ho[warp];
    }
    __syncthreads();

    if (tid == 0) {
        float l[4], e[4];
        float m = -FLT_MAX;
#pragma unroll
        for (int o = 0; o < 4; o++) { l[o] = s_logits[0][o]; m = fmaxf(m, l[o]); }
        float sum = 0.f;
#pragma unroll
        for (int o = 0; o < 4; o++) { e[o] = expf(l[o] - m); sum += e[o]; }
        float logsum = logf(sum);
        float inv = 1.f / sum;
        bool used[4] = {false, false, false, false};
        for (int b = 0; b < 4; b++) {
            int best = -1; float bv = -FLT_MAX;
            for (int o = 0; o < 4; o++) {
                float lp = l[o] - m - logsum;
                if (!used[o] && lp > bv) { bv = lp; best = o; }
            }
            used[best] = true;
            s_scores[b] = bv;
            s_op[b] = best;
            g_op[0 * (NB * 4) + n * 4 + b] = best;
            g_pv[0 * (NB * 4) + n * 4 + b] = e[best] * inv;
        }
    }
    __syncthreads();

    {
        float common = 0.f;
#pragma unroll 8
        for (int k = 0; k < 128; k++) common += s_h0[k] * W_hh[k * 128 + tid];
        float bh = b_h[tid];
#pragma unroll
        for (int b = 0; b < 4; b++)
            s_h[b][tid] = tanhf(common + E_op[s_op[b] * 128 + tid] + bh);
    }
    __syncthreads();

    for (int step = 1; step < 3; step++) {
        {
            float a0 = 0.f, a1 = 0.f, a2 = 0.f, a3 = 0.f;
            for (int d = lane; d < 128; d += 32) {
                float v = s_h[warp][d];
                a0 += v * s_Who[d * 4 + 0];
                a1 += v * s_Who[d * 4 + 1];
                a2 += v * s_Who[d * 4 + 2];
                a3 += v * s_Who[d * 4 + 3];
            }
            a0 = warp_sum(a0); a1 = warp_sum(a1); a2 = warp_sum(a2); a3 = warp_sum(a3);
            if (lane == 0) {
                s_logits[warp][0] = a0 + b_ho[0];
                s_logits[warp][1] = a1 + b_ho[1];
                s_logits[warp][2] = a2 + b_ho[2];
                s_logits[warp][3] = a3 + b_ho[3];
            }
        }
        __syncthreads();

        if (tid == 0) {
            float cand[16], probs[16];
            for (int b = 0; b < 4; b++) {
                float l[4], e[4];
                float m = -FLT_MAX;
#pragma unroll
                for (int o = 0; o < 4; o++) { l[o] = s_logits[b][o]; m = fmaxf(m, l[o]); }
                float sum = 0.f;
#pragma unroll
                for (int o = 0; o < 4; o++) { e[o] = expf(l[o] - m); sum += e[o]; }
                float logsum = logf(sum);
                float inv = 1.f / sum;
#pragma unroll
                for (int o = 0; o < 4; o++) {
                    cand[b * 4 + o] = s_scores[b] + (l[o] - m - logsum);
                    probs[b * 4 + o] = e[o] * inv;
                }
            }
            bool used[16];
            for (int i = 0; i < 16; i++) used[i] = false;
            float ns[4];
            for (int b = 0; b < 4; b++) {
                int best = -1; float bv = -FLT_MAX;
                for (int f = 0; f < 16; f++)
                    if (!used[f] && cand[f] > bv) { bv = cand[f]; best = f; }
                used[best] = true;
                ns[b] = bv;
                int src = best >> 2, op = best & 3;
                s_src[b] = src; s_op[b] = op;
                g_op[step * (NB * 4) + n * 4 + b] = op;
                g_pv[step * (NB * 4) + n * 4 + b] = probs[best];
            }
#pragma unroll
            for (int b = 0; b < 4; b++) s_scores[b] = ns[b];
        }
        __syncthreads();

        if (step < 2) {
            int r0 = s_src[0], r1 = s_src[1], r2 = s_src[2], r3 = s_src[3];
            float a0 = 0.f, a1 = 0.f, a2 = 0.f, a3 = 0.f;
#pragma unroll 4
            for (int k = 0; k < 128; k++) {
                float wv = W_hh[k * 128 + tid];
                a0 += s_h[r0][k] * wv;
                a1 += s_h[r1][k] * wv;
                a2 += s_h[r2][k] * wv;
                a3 += s_h[r3][k] * wv;
            }
            float bh = b_h[tid];
            s_hn[0][tid] = tanhf(a0 + E_op[s_op[0] * 128 + tid] + bh);
            s_hn[1][tid] = tanhf(a1 + E_op[s_op[1] * 128 + tid] + bh);
            s_hn[2][tid] = tanhf(a2 + E_op[s_op[2] * 128 + tid] + bh);
            s_hn[3][tid] = tanhf(a3 + E_op[s_op[3] * 128 + tid] + bh);
            __syncthreads();
#pragma unroll
            for (int b = 0; b < 4; b++) s_h[b][tid] = s_hn[b][tid];
            __syncthreads();
        }
    }

    // fused MoE bucketing
    if (tid < 12) {
        int step = tid >> 2, b = tid & 3;
        int m = n * 4 + b;
        int op = g_op[step * (NB * 4) + m];
        float p = g_pv[step * (NB * 4) + m];
        int e = (p > 0.f) ? op : 0;
        int pos = atomicAdd(&g_cnt[step][e], 1);
        g_ridx[(step * 4 + e) * (NB * 4) + pos] = m;
    }
}

// ---------------------- sorted MoE dispatch --------------------------------
// One step of dispatch, 32 rows/block (8 accumulators -> no spills).
// step==2 additionally computes the final 128->10 projection from smem and
// resets g_ctr1 for the next graph replay.
__global__ __launch_bounds__(256) void moe_step_kernel(
    const float* __restrict__ exp_w, const float* __restrict__ exp_b,
    const float* __restrict__ out_w, const float* __restrict__ out_b,
    float* __restrict__ out, int step)
{
    extern __shared__ float sm[];
    float* s_w = sm;              // 16384 floats
    float* buf = sm + 16384;      // 32 x 128
    float* s_outw = sm + 20480;   // 1280 floats (step==2 only)
    __shared__ float s_b[128];
    __shared__ float s_outb[10];
    __shared__ int   s_rows[32];
    __shared__ float s_p[32];
    __shared__ int   s_cnt;

    int e = blockIdx.y;
    int tid = threadIdx.x;
    if (step == 2 && blockIdx.x == 0 && blockIdx.y == 0 && tid == 0)
        g_ctr1 = 0u;   // reset conv1 work counter for the next replay
    if (tid == 0) s_cnt = g_cnt[step][e];
    __syncthreads();
    int base = blockIdx.x * 32;
    if (base >= s_cnt) return;
    int nrows = min(32, s_cnt - base);

    if (tid < nrows) {
        int m = g_ridx[(step * 4 + e) * (NB * 4) + base + tid];
        s_rows[tid] = m;
        s_p[tid] = g_pv[step * (NB * 4) + m];
    }
    if (step == 2) {
        for (int i = tid; i < 1280; i += 256) s_outw[i] = out_w[i];
        if (tid < 10) s_outb[tid] = out_b[tid];
    }
    __syncthreads();

    if (e == 3) {   // identity: out = relu(hid * p)
        if (step < 2) {
            for (int i = tid; i < nrows * 128; i += 256) {
                int r = i >> 7, j = i & 127;
                int m = s_rows[r];
                float v = (step == 0) ? g_h0[(size_t)(m >> 2) * 128 + j]
                                      : g_hid[(size_t)m * 128 + j];
                g_hid[(size_t)m * 128 + j] = fmaxf(v * s_p[r], 0.f);
            }
            return;
        }
        for (int i = tid; i < nrows * 128; i += 256) {
            int r = i >> 7, j = i & 127;
            float v = g_hid[(size_t)s_rows[r] * 128 + j];
            buf[i] = fmaxf(v * s_p[r], 0.f);
        }
        __syncthreads();
        for (int i = tid; i < nrows * 10; i += 256) {
            int r = i / 10, o = i % 10;
            float a = s_outb[o];
            const float* hp = buf + r * 128;
#pragma unroll 8
            for (int d = 0; d < 128; d++) a += hp[d] * s_outw[d * 10 + o];
            out[(size_t)s_rows[r] * 10 + o] = a;
        }
        return;
    }

    for (int i = tid; i < 16384; i += 256) s_w[i] = exp_w[e * 16384 + i];
    if (tid < 128) s_b[tid] = exp_b[e * 128 + tid];
    for (int i = tid; i < 4096; i += 256) {
        int r = i >> 7, j = i & 127;
        float v = 0.f;
        if (r < nrows) {
            int m = s_rows[r];
            v = (step == 0) ? g_h0[(size_t)(m >> 2) * 128 + j]
                            : g_hid[(size_t)m * 128 + j];
        }
        buf[i] = v;
    }
    __syncthreads();

    int cp = tid & 63, rowg = tid >> 6;
    int r0 = rowg * 8, j0 = cp * 2;
    u64t acc[8];
#pragma unroll
    for (int k = 0; k < 8; k++) acc[k] = 0ull;
    for (int d = 0; d < 128; d += 4) {
        u64t w0 = *(const u64t*)(s_w + (d + 0) * 128 + j0);
        u64t w1 = *(const u64t*)(s_w + (d + 1) * 128 + j0);
        u64t w2 = *(const u64t*)(s_w + (d + 2) * 128 + j0);
        u64t w3 = *(const u64t*)(s_w + (d + 3) * 128 + j0);
#pragma unroll
        for (int k = 0; k < 8; k++) {
            float4 h = *(const float4*)(buf + (r0 + k) * 128 + d);
            ffma2(acc[k], w0, splat2(h.x));
            ffma2(acc[k], w1, splat2(h.y));
            ffma2(acc[k], w2, splat2(h.z));
            ffma2(acc[k], w3, splat2(h.w));
        }
    }
    u64t b2 = *(const u64t*)(s_b + j0);

    if (step < 2) {
#pragma unroll
        for (int k = 0; k < 8; k++) {
            int r = r0 + k;
            if (r < nrows) {
                int m = s_rows[r];
                float v = s_p[r];
                float2 st;
                st.x = fmaxf((lo32(acc[k]) + lo32(b2)) * v, 0.f);
                st.y = fmaxf((hi32(acc[k]) + hi32(b2)) * v, 0.f);
                *(float2*)(g_hid + (size_t)m * 128 + j0) = st;
            }
        }
        return;
    }

    // step==2: write results back into buf, then project
    __syncthreads();   // all reads of buf done
#pragma unroll
    for (int k = 0; k < 8; k++) {
        int r = r0 + k;
        float v = s_p[r < nrows ? r : 0];
        float2 st;
        st.x = fmaxf((lo32(acc[k]) + lo32(b2)) * v, 0.f);
        st.y = fmaxf((hi32(acc[k]) + hi32(b2)) * v, 0.f);
        *(float2*)(buf + r * 128 + j0) = st;
    }
    __syncthreads();
    for (int i = tid; i < nrows * 10; i += 256) {
        int r = i / 10, o = i % 10;
        float a = s_outb[o];
        const float* hp = buf + r * 128;
#pragma unroll 8
        for (int d = 0; d < 128; d++) a += hp[d] * s_outw[d * 10 + o];
        out[(size_t)s_rows[r] * 10 + o] = a;
    }
}

// ---------------------------------------------------------------------------
extern "C" void kernel_launch(void* const* d_in, const int* in_sizes, int n_in,
                              void* d_out, int out_size)
{
    const float* x    = (const float*)d_in[0];
    const float* cw1  = (const float*)d_in[1];
    const float* cb1  = (const float*)d_in[2];
    const float* g1   = (const float*)d_in[3];
    const float* be1  = (const float*)d_in[4];
    const float* cw2  = (const float*)d_in[5];
    const float* cb2  = (const float*)d_in[6];
    const float* g2   = (const float*)d_in[7];
    const float* be2  = (const float*)d_in[8];
    const float* cw3  = (const float*)d_in[9];
    const float* cb3  = (const float*)d_in[10];
    const float* g3   = (const float*)d_in[11];
    const float* be3  = (const float*)d_in[12];
    const float* W_hh = (const float*)d_in[13];
    const float* b_h  = (const float*)d_in[14];
    const float* E_op = (const float*)d_in[15];
    const float* W_ho = (const float*)d_in[16];
    const float* b_ho = (const float*)d_in[17];
    const float* expw = (const float*)d_in[18];
    const float* expb = (const float*)d_in[19];
    const float* outw = (const float*)d_in[20];
    const float* outb = (const float*)d_in[21];
    float* out = (float*)d_out;

    cudaFuncSetAttribute(conv2_kernel, cudaFuncAttributeMaxDynamicSharedMemorySize,
                         (15360 + 9216) * 4);
    cudaFuncSetAttribute(conv3_kernel, cudaFuncAttributeMaxDynamicSharedMemorySize,
                         (6144 + 9216) * 4);
    cudaFuncSetAttribute(moe_step_kernel, cudaFuncAttributeMaxDynamicSharedMemorySize,
                         (16384 + 4096 + 1280) * 4);

    conv1_kernel<<<152, 960>>>(x, cw1, cb1);
    reduce_stats_kernel<<<32, 256>>>(0, 1.f / (NB * 900.f), g1, be1);

    conv2_kernel<<<304, 448, (15360 + 9216) * 4>>>(cw2, cb2);
    reduce_stats_kernel<<<32, 256>>>(1, 1.f / (NB * 169.f), g2, be2);

    conv3_kernel<<<456, 256, (6144 + 9216) * 4>>>(cw3, cb3);
    reduce_stats_kernel<<<32, 256>>>(2, 1.f / (NB * 16.f), g3, be3);

    beam_kernel<<<NB, 128>>>(W_hh, b_h, E_op, W_ho, b_ho);

    dim3 moe_grid(NB * 4 / 32, 4);
    size_t moe_smem = (16384 + 4096 + 1280) * 4;
    moe_step_kernel<<<moe_grid, 256, moe_smem>>>(expw, expb, outw, outb, out, 0);
    moe_step_kernel<<<moe_grid, 256, moe_smem>>>(expw, expb, outw, outb, out, 1);
    moe_step_kernel<<<moe_grid, 256, moe_smem>>>(expw, expb, outw, outb, out, 2);
}